// round 1
// baseline (speedup 1.0000x reference)
#include <cuda_runtime.h>
#include <math.h>

#define TOK   65536       // B * H * W = 16*64*64
#define CH    256
#define HEADS 8
#define HD    32
#define WS    8
#define MLPH  1024

// ---------------- scratch (static device globals; no allocation) -----------
__device__ float g_ln  [TOK * CH];        //  64 MB
__device__ float g_qkv [TOK * 3 * CH];    // 192 MB
__device__ float g_att [TOK * CH];        //  64 MB
__device__ float g_x   [TOK * CH];        //  64 MB
__device__ float g_y   [TOK * CH];        //  64 MB
__device__ float g_mlp [TOK * MLPH];      // 256 MB

// ---------------- LayerNorm: one block (256 thr) per token -----------------
__global__ void ln_kernel(const float* __restrict__ in, const float* __restrict__ gam,
                          const float* __restrict__ bet, float* __restrict__ out) {
    int t = blockIdx.x, c = threadIdx.x;
    float v = in[(size_t)t * CH + c];
    __shared__ float red[8];
    __shared__ float mu_s, var_s;

    float s = v;
    #pragma unroll
    for (int o = 16; o; o >>= 1) s += __shfl_xor_sync(0xffffffffu, s, o);
    if ((c & 31) == 0) red[c >> 5] = s;
    __syncthreads();
    if (c == 0) {
        float tot = 0.f;
        #pragma unroll
        for (int i = 0; i < 8; i++) tot += red[i];
        mu_s = tot * (1.0f / CH);
    }
    __syncthreads();
    float mu = mu_s;
    float d = v - mu;
    s = d * d;
    #pragma unroll
    for (int o = 16; o; o >>= 1) s += __shfl_xor_sync(0xffffffffu, s, o);
    if ((c & 31) == 0) red[c >> 5] = s;
    __syncthreads();
    if (c == 0) {
        float tot = 0.f;
        #pragma unroll
        for (int i = 0; i < 8; i++) tot += red[i];
        var_s = tot * (1.0f / CH);
    }
    __syncthreads();
    out[(size_t)t * CH + c] = d * rsqrtf(var_s + 1e-5f) * gam[c] + bet[c];
}

// ---------------- fp32 tiled GEMM: out = A[M,K] @ W[K,N] + bias (+epi) -----
// EPI: 0 = bias only, 1 = bias + exact GELU, 2 = bias + residual add
__device__ __forceinline__ float gelu_exact(float x) {
    return 0.5f * x * (1.0f + erff(x * 0.7071067811865476f));
}

template <int EPI>
__global__ __launch_bounds__(256)
void gemm_kernel(const float* __restrict__ A, const float* __restrict__ W,
                 const float* __restrict__ bias, const float* __restrict__ res,
                 float* __restrict__ out, int M, int N, int K) {
    __shared__ float As[16][64];
    __shared__ float Bs[16][64];
    const int tid = threadIdx.x;
    const int tx = tid & 15, ty = tid >> 4;
    const int m0 = blockIdx.y << 6, n0 = blockIdx.x << 6;

    float acc[4][4] = {};

    const int am = tid >> 2,  ak = (tid & 3)  << 2;   // A tile: 64 rows x 16 k
    const int bk = tid >> 4,  bn = (tid & 15) << 2;   // B tile: 16 k   x 64 n
    const float* Aptr = A + (size_t)(m0 + am) * K + ak;
    const float* Wptr = W + (size_t)bk * N + n0 + bn;

    for (int k0 = 0; k0 < K; k0 += 16) {
        float4 av = *(const float4*)(Aptr + k0);
        float4 bv = *(const float4*)(Wptr + (size_t)k0 * N);
        As[ak + 0][am] = av.x;
        As[ak + 1][am] = av.y;
        As[ak + 2][am] = av.z;
        As[ak + 3][am] = av.w;
        *(float4*)&Bs[bk][bn] = bv;
        __syncthreads();
        #pragma unroll
        for (int k = 0; k < 16; k++) {
            float4 a4 = *(const float4*)&As[k][ty << 2];
            float4 b4 = *(const float4*)&Bs[k][tx << 2];
            float ar[4] = {a4.x, a4.y, a4.z, a4.w};
            float br[4] = {b4.x, b4.y, b4.z, b4.w};
            #pragma unroll
            for (int i = 0; i < 4; i++)
                #pragma unroll
                for (int j = 0; j < 4; j++)
                    acc[i][j] += ar[i] * br[j];
        }
        __syncthreads();
    }

    float4 b4 = *(const float4*)&bias[n0 + (tx << 2)];
    float bb[4] = {b4.x, b4.y, b4.z, b4.w};
    #pragma unroll
    for (int i = 0; i < 4; i++) {
        int r = m0 + (ty << 2) + i;
        size_t off = (size_t)r * N + n0 + (tx << 2);
        float o[4];
        #pragma unroll
        for (int j = 0; j < 4; j++) o[j] = acc[i][j] + bb[j];
        if (EPI == 1) {
            #pragma unroll
            for (int j = 0; j < 4; j++) o[j] = gelu_exact(o[j]);
        }
        if (EPI == 2) {
            float4 rv = *(const float4*)&res[off];
            o[0] += rv.x; o[1] += rv.y; o[2] += rv.z; o[3] += rv.w;
        }
        float4 ov = {o[0], o[1], o[2], o[3]};
        *(float4*)&out[off] = ov;
    }
}

// ---------------- windowed attention: one block per (head, window, batch) --
// Shift/window permutation folded into the gather index; mask computed from
// region codes on shifted coordinates; rel-pos bias cached per-head in smem.
template <int SHIFT>
__global__ __launch_bounds__(64)
void attn_kernel(const float* __restrict__ qkv, const float* __restrict__ rpb,
                 float* __restrict__ out) {
    const int head = blockIdx.x;        // 8
    const int win  = blockIdx.y;        // 64
    const int b    = blockIdx.z;        // 16
    const int wy = win >> 3, wx = win & 7;
    const int n = threadIdx.x;          // token in window
    const int r = n >> 3, c = n & 7;

    __shared__ float Ks[64][HD];
    __shared__ float Vs[64][HD];
    __shared__ float sbias[225];
    __shared__ int   scode[64];

    // shifted coords -> natural coords (roll cancels with window reverse+unroll)
    const int sy = wy * WS + r, sx = wx * WS + c;
    const int y  = (sy + SHIFT) & 63;
    const int x  = (sx + SHIFT) & 63;
    const int t  = b * 4096 + y * 64 + x;

    const float* base = qkv + (size_t)t * (3 * CH) + head * HD;
    float q[HD];
    #pragma unroll
    for (int d = 0; d < HD; d++) q[d] = base[d] * 0.17677669529663687f;  // HD^-0.5
    #pragma unroll
    for (int d = 0; d < HD; d++) Ks[n][d] = base[CH + d];
    #pragma unroll
    for (int d = 0; d < HD; d++) Vs[n][d] = base[2 * CH + d];

    if (SHIFT) {
        int ry = sy < 56 ? 0 : (sy < 60 ? 1 : 2);
        int rx = sx < 56 ? 0 : (sx < 60 ? 1 : 2);
        scode[n] = ry * 3 + rx;
    }
    for (int i = n; i < 225; i += 64) sbias[i] = rpb[i * HEADS + head];
    __syncthreads();

    float s[64];
    const int mycode = SHIFT ? scode[n] : 0;
    #pragma unroll
    for (int m = 0; m < 64; m++) {
        float a = 0.f;
        #pragma unroll
        for (int d = 0; d < HD; d++) a += q[d] * Ks[m][d];
        int r2 = m >> 3, c2 = m & 7;
        a += sbias[(r - r2 + 7) * 15 + (c - c2 + 7)];
        if (SHIFT) { if (mycode != scode[m]) a -= 100.0f; }
        s[m] = a;
    }

    float mx = -1e30f;
    #pragma unroll
    for (int m = 0; m < 64; m++) mx = fmaxf(mx, s[m]);
    float sum = 0.f;
    #pragma unroll
    for (int m = 0; m < 64; m++) { s[m] = expf(s[m] - mx); sum += s[m]; }
    const float inv = 1.0f / sum;

    float acc[HD] = {};
    #pragma unroll
    for (int m = 0; m < 64; m++) {
        float p = s[m] * inv;
        #pragma unroll
        for (int d = 0; d < HD; d++) acc[d] += p * Vs[m][d];
    }

    float* op = out + (size_t)t * CH + head * HD;
    #pragma unroll
    for (int d = 0; d < HD; d++) op[d] = acc[d];
}

// ---------------- host orchestration ---------------------------------------
static void run_block(const float* xin, const float* const* p, float* xout,
                      int shift, float* ln, float* qkv, float* att, float* mlp) {
    // p[0..12] = n1g n1b qkvw qkvb rpb pw pb n2g n2b f1w f1b f2w f2b
    ln_kernel<<<TOK, 256>>>(xin, p[0], p[1], ln);
    gemm_kernel<0><<<dim3(768 / 64, TOK / 64), 256>>>(ln, p[2], p[3], nullptr, qkv,
                                                      TOK, 768, CH);
    if (shift)
        attn_kernel<4><<<dim3(HEADS, 64, 16), 64>>>(qkv, p[4], att);
    else
        attn_kernel<0><<<dim3(HEADS, 64, 16), 64>>>(qkv, p[4], att);
    gemm_kernel<2><<<dim3(CH / 64, TOK / 64), 256>>>(att, p[5], p[6], xin, xout,
                                                     TOK, CH, CH);
    ln_kernel<<<TOK, 256>>>(xout, p[7], p[8], ln);
    gemm_kernel<1><<<dim3(MLPH / 64, TOK / 64), 256>>>(ln, p[9], p[10], nullptr, mlp,
                                                       TOK, MLPH, CH);
    // fc2 residual = xout, written in-place per-element (safe RMW)
    // (output pointer supplied by caller below)
}

extern "C" void kernel_launch(void* const* d_in, const int* in_sizes, int n_in,
                              void* d_out, int out_size) {
    const float* x = (const float*)d_in[0];
    const float* p0[13];
    const float* p1[13];
    for (int i = 0; i < 13; i++) p0[i] = (const float*)d_in[1 + i];
    for (int i = 0; i < 13; i++) p1[i] = (const float*)d_in[14 + i];

    float *ln, *qkv, *att, *xb, *yb, *mlp;
    cudaGetSymbolAddress((void**)&ln,  g_ln);
    cudaGetSymbolAddress((void**)&qkv, g_qkv);
    cudaGetSymbolAddress((void**)&att, g_att);
    cudaGetSymbolAddress((void**)&xb,  g_x);
    cudaGetSymbolAddress((void**)&yb,  g_y);
    cudaGetSymbolAddress((void**)&mlp, g_mlp);

    // ---- block 0 (W-MSA, shift=0) ----
    run_block(x, p0, xb, 0, ln, qkv, att, mlp);
    gemm_kernel<2><<<dim3(CH / 64, TOK / 64), 256>>>(mlp, p0[11], p0[12], xb, xb,
                                                     TOK, CH, MLPH);

    // ---- block 1 (SW-MSA, shift=4, masked) ----
    run_block(xb, p1, yb, 4, ln, qkv, att, mlp);
    gemm_kernel<2><<<dim3(CH / 64, TOK / 64), 256>>>(mlp, p1[11], p1[12], yb,
                                                     (float*)d_out, TOK, CH, MLPH);
}

// round 7
// speedup vs baseline: 1.8576x; 1.8576x over previous
#include <cuda_runtime.h>
#include <cuda_bf16.h>
#include <math.h>
#include <stdint.h>

#define TOK   65536
#define CH    256
#define HEADS 8
#define HD    32
#define WS    8
#define MLPH  1024

// ---------------- scratch (static device globals; no allocation) -----------
__device__ float          g_qkv [TOK * 3 * CH];          // fp32 qkv
__device__ float          g_x   [TOK * CH];              // residual stream
__device__ float          g_y   [TOK * CH];
__device__ __nv_bfloat16  g_lnh [TOK * CH];
__device__ __nv_bfloat16  g_lnl [TOK * CH];
__device__ __nv_bfloat16  g_ath [TOK * CH];
__device__ __nv_bfloat16  g_atl [TOK * CH];
__device__ __nv_bfloat16  g_mph [TOK * MLPH];
__device__ __nv_bfloat16  g_mpl [TOK * MLPH];
#define WT_BLK 786432
__device__ __nv_bfloat16  g_wth [2 * WT_BLK];
__device__ __nv_bfloat16  g_wtl [2 * WT_BLK];

// ======================= small PTX helpers =================================
__device__ __forceinline__ uint32_t smem_u32(const void* p) {
    uint32_t a;
    asm("{ .reg .u64 t; cvta.to.shared.u64 t, %1; cvt.u32.u64 %0, t; }" : "=r"(a) : "l"(p));
    return a;
}
__device__ __forceinline__ void cp16(uint32_t s, const void* g) {
    asm volatile("cp.async.ca.shared.global [%0], [%1], 16;" :: "r"(s), "l"(g));
}
#define CP_COMMIT() asm volatile("cp.async.commit_group;" ::: "memory")
#define CP_WAIT(n)  asm volatile("cp.async.wait_group %0;" :: "n"(n) : "memory")

__device__ __forceinline__ void ld_x4(uint32_t* r, uint32_t addr) {
    asm volatile("ldmatrix.sync.aligned.m8n8.x4.shared.b16 {%0,%1,%2,%3}, [%4];"
                 : "=r"(r[0]), "=r"(r[1]), "=r"(r[2]), "=r"(r[3]) : "r"(addr));
}
__device__ __forceinline__ void mma16816(float* c, const uint32_t* a, const uint32_t* b) {
    asm volatile("mma.sync.aligned.m16n8k16.row.col.f32.bf16.bf16.f32 "
                 "{%0,%1,%2,%3}, {%4,%5,%6,%7}, {%8,%9}, {%0,%1,%2,%3};"
                 : "+f"(c[0]), "+f"(c[1]), "+f"(c[2]), "+f"(c[3])
                 : "r"(a[0]), "r"(a[1]), "r"(a[2]), "r"(a[3]), "r"(b[0]), "r"(b[1]));
}
__device__ __forceinline__ void split_bf16(float v, __nv_bfloat16& h, __nv_bfloat16& l) {
    h = __float2bfloat16(v);
    l = __float2bfloat16(v - __bfloat162float(h));
}
__device__ __forceinline__ float gelu_exact(float x) {
    return 0.5f * x * (1.0f + erff(x * 0.7071067811865476f));
}

// ======================= LayerNorm (emits hi/lo bf16) ======================
__global__ void ln_kernel(const float* __restrict__ in, const float* __restrict__ gam,
                          const float* __restrict__ bet,
                          __nv_bfloat16* __restrict__ oh, __nv_bfloat16* __restrict__ ol) {
    int t = blockIdx.x, c = threadIdx.x;
    float v = in[(size_t)t * CH + c];
    __shared__ float red[8];
    __shared__ float mu_s, var_s;
    float s = v;
    #pragma unroll
    for (int o = 16; o; o >>= 1) s += __shfl_xor_sync(0xffffffffu, s, o);
    if ((c & 31) == 0) red[c >> 5] = s;
    __syncthreads();
    if (c == 0) { float tt = 0.f; for (int i = 0; i < 8; i++) tt += red[i]; mu_s = tt * (1.f / CH); }
    __syncthreads();
    float d = v - mu_s;
    s = d * d;
    #pragma unroll
    for (int o = 16; o; o >>= 1) s += __shfl_xor_sync(0xffffffffu, s, o);
    if ((c & 31) == 0) red[c >> 5] = s;
    __syncthreads();
    if (c == 0) { float tt = 0.f; for (int i = 0; i < 8; i++) tt += red[i]; var_s = tt * (1.f / CH); }
    __syncthreads();
    float o = d * rsqrtf(var_s + 1e-5f) * gam[c] + bet[c];
    __nv_bfloat16 h, l;
    split_bf16(o, h, l);
    oh[(size_t)t * CH + c] = h;
    ol[(size_t)t * CH + c] = l;
}

// ========== weight prep: W[K,N] -> Wt_hi[N,K], Wt_lo[N,K] (bf16) ===========
__global__ void transpose_split(const float* __restrict__ W, __nv_bfloat16* __restrict__ th,
                                __nv_bfloat16* __restrict__ tl, int K, int N) {
    __shared__ float t[32][33];
    int nb = blockIdx.x << 5, kb = blockIdx.y << 5;
    #pragma unroll
    for (int i = 0; i < 32; i += 8)
        t[threadIdx.y + i][threadIdx.x] = W[(size_t)(kb + threadIdx.y + i) * N + nb + threadIdx.x];
    __syncthreads();
    #pragma unroll
    for (int i = 0; i < 32; i += 8) {
        float v = t[threadIdx.x][threadIdx.y + i];
        __nv_bfloat16 h, l;
        split_bf16(v, h, l);
        size_t off = (size_t)(nb + threadIdx.y + i) * K + kb + threadIdx.x;
        th[off] = h; tl[off] = l;
    }
}

// ======================= split-bf16 HMMA GEMM ==============================
// C[M,N] = A @ Wt^T (3-pass: Ah*Bh + Ah*Bl + Al*Bh), bias + epilogue.
// EPI: 0 = fp32 out;  1 = GELU -> (hi,lo) bf16 out;  2 = +res -> fp32 out.
#define KC 32
#define TS 40                         // smem row stride in halves (80 B)
#define TILE_B (128 * TS * 2)         // 10240 B per tile
#define STAGE_B (4 * TILE_B)          // Ah, Al, Bh, Bl
#define SM_BIAS (2 * STAGE_B)
#define SM_DYN  (SM_BIAS + 512)

template <int EPI>
__global__ __launch_bounds__(256, 1)
void tc_gemm(const __nv_bfloat16* __restrict__ Ah, const __nv_bfloat16* __restrict__ Al,
             const __nv_bfloat16* __restrict__ Bh, const __nv_bfloat16* __restrict__ Bl,
             const float* __restrict__ bias, const float* __restrict__ res,
             float* __restrict__ out, __nv_bfloat16* __restrict__ outh,
             __nv_bfloat16* __restrict__ outl, int M, int N, int K) {
    extern __shared__ char sm[];
    const uint32_t sb = smem_u32(sm);
    const int tid = threadIdx.x, wid = tid >> 5, lane = tid & 31;
    const int n0 = blockIdx.x << 7, m0 = blockIdx.y << 7;
    const int mw = wid >> 2, nw = wid & 3;          // warp grid 2x4 -> 64x32 tiles

    float* sbias = (float*)(sm + SM_BIAS);
    if (tid < 128) sbias[tid] = bias[n0 + tid];

    // ---- async load of one pipeline stage ----
    const int lrow = tid >> 2, lc = tid & 3;        // 2 iters cover 128 rows
    auto load_stage = [&](int s, int kc) {
        const int k0 = kc << 5;
        uint32_t base = sb + s * STAGE_B;
        #pragma unroll
        for (int i = 0; i < 2; i++) {
            int row = lrow + i * 64;
            uint32_t so = row * (TS * 2) + lc * 16;
            size_t ga = (size_t)(m0 + row) * K + k0 + lc * 8;
            size_t gb = (size_t)(n0 + row) * K + k0 + lc * 8;
            cp16(base + 0 * TILE_B + so, Ah + ga);
            cp16(base + 1 * TILE_B + so, Al + ga);
            cp16(base + 2 * TILE_B + so, Bh + gb);
            cp16(base + 3 * TILE_B + so, Bl + gb);
        }
    };

    float acc[4][4][4] = {};                        // [mfrag][nfrag][4]

    // ldmatrix per-lane address bases
    const int li = lane & 7, lm = lane >> 3;
    const uint32_t aRB = (mw * 64 + (lm & 1) * 8 + li) * (TS * 2) + ((lm >> 1) * 8) * 2;
    const uint32_t bRB = (nw * 32 + (lm >> 1) * 8 + li) * (TS * 2) + ((lm & 1) * 8) * 2;

    const int nch = K >> 5;
    load_stage(0, 0);
    CP_COMMIT();

    for (int kc = 0; kc < nch; kc++) {
        const int s = kc & 1;
        if (kc + 1 < nch) { load_stage(s ^ 1, kc + 1); CP_COMMIT(); CP_WAIT(1); }
        else CP_WAIT(0);
        __syncthreads();

        const uint32_t sA  = sb + s * STAGE_B;
        const uint32_t sAl = sA + TILE_B;
        const uint32_t sB  = sA + 2 * TILE_B;
        const uint32_t sBl = sA + 3 * TILE_B;

        #pragma unroll
        for (int kk = 0; kk < 2; kk++) {
            const uint32_t ko = kk * 32;            // 16 halves = 32 B
            uint32_t ah[16], al[16], bh[8], bl[8];
            #pragma unroll
            for (int mg = 0; mg < 4; mg++) ld_x4(ah + mg * 4, sA + aRB + mg * 16 * (TS * 2) + ko);
            #pragma unroll
            for (int ng = 0; ng < 2; ng++) ld_x4(bh + ng * 4, sB + bRB + ng * 16 * (TS * 2) + ko);
            #pragma unroll
            for (int mg = 0; mg < 4; mg++)
                #pragma unroll
                for (int j = 0; j < 4; j++)
                    mma16816(acc[mg][j], ah + mg * 4, bh + (j >> 1) * 4 + (j & 1) * 2);
            #pragma unroll
            for (int ng = 0; ng < 2; ng++) ld_x4(bl + ng * 4, sBl + bRB + ng * 16 * (TS * 2) + ko);
            #pragma unroll
            for (int mg = 0; mg < 4; mg++)
                #pragma unroll
                for (int j = 0; j < 4; j++)
                    mma16816(acc[mg][j], ah + mg * 4, bl + (j >> 1) * 4 + (j & 1) * 2);
            #pragma unroll
            for (int mg = 0; mg < 4; mg++) ld_x4(al + mg * 4, sAl + aRB + mg * 16 * (TS * 2) + ko);
            #pragma unroll
            for (int mg = 0; mg < 4; mg++)
                #pragma unroll
                for (int j = 0; j < 4; j++)
                    mma16816(acc[mg][j], al + mg * 4, bh + (j >> 1) * 4 + (j & 1) * 2);
        }
        __syncthreads();
    }

    // ---- epilogue: regs -> smem (fp32) -> coalesced gmem ----
    float* sacc = (float*)sm;                       // 128 x 132 floats
    const int fr = lane >> 2, fc = (lane & 3) * 2;
    #pragma unroll
    for (int mg = 0; mg < 4; mg++)
        #pragma unroll
        for (int j = 0; j < 4; j++) {
            int row = mw * 64 + mg * 16 + fr;
            int col = nw * 32 + j * 8 + fc;
            sacc[row * 132 + col]       = acc[mg][j][0];
            sacc[row * 132 + col + 1]   = acc[mg][j][1];
            sacc[(row + 8) * 132 + col]     = acc[mg][j][2];
            sacc[(row + 8) * 132 + col + 1] = acc[mg][j][3];
        }
    __syncthreads();

    const float4 b4 = *(const float4*)&sbias[lane * 4];
    #pragma unroll 4
    for (int it = 0; it < 16; it++) {
        int r = it * 8 + wid;
        float4 v = *(const float4*)&sacc[r * 132 + lane * 4];
        v.x += b4.x; v.y += b4.y; v.z += b4.z; v.w += b4.w;
        size_t off = (size_t)(m0 + r) * N + n0 + lane * 4;
        if (EPI == 0) {
            *(float4*)&out[off] = v;
        } else if (EPI == 1) {
            v.x = gelu_exact(v.x); v.y = gelu_exact(v.y);
            v.z = gelu_exact(v.z); v.w = gelu_exact(v.w);
            __nv_bfloat16 h[4], l[4];
            split_bf16(v.x, h[0], l[0]); split_bf16(v.y, h[1], l[1]);
            split_bf16(v.z, h[2], l[2]); split_bf16(v.w, h[3], l[3]);
            *(uint2*)&outh[off] = *(uint2*)h;
            *(uint2*)&outl[off] = *(uint2*)l;
        } else {
            float4 rv = *(const float4*)&res[off];
            v.x += rv.x; v.y += rv.y; v.z += rv.z; v.w += rv.w;
            *(float4*)&out[off] = v;
        }
    }
}

// ======================= windowed attention (fp32, emits hi/lo) ============
template <int SHIFT>
__global__ __launch_bounds__(64)
void attn_kernel(const float* __restrict__ qkv, const float* __restrict__ rpb,
                 __nv_bfloat16* __restrict__ outh, __nv_bfloat16* __restrict__ outl) {
    const int head = blockIdx.x, win = blockIdx.y, b = blockIdx.z;
    const int wy = win >> 3, wx = win & 7;
    const int n = threadIdx.x;
    const int r = n >> 3, c = n & 7;

    __shared__ float Ks[64][HD];
    __shared__ float Vs[64][HD];
    __shared__ float sbias[225];
    __shared__ int   scode[64];

    const int sy = wy * WS + r, sx = wx * WS + c;
    const int y = (sy + SHIFT) & 63;
    const int x = (sx + SHIFT) & 63;
    const int t = b * 4096 + y * 64 + x;

    const float* base = qkv + (size_t)t * (3 * CH) + head * HD;
    float q[HD];
    #pragma unroll
    for (int d = 0; d < HD; d++) q[d] = base[d] * 0.17677669529663687f;
    #pragma unroll
    for (int d = 0; d < HD; d++) Ks[n][d] = base[CH + d];
    #pragma unroll
    for (int d = 0; d < HD; d++) Vs[n][d] = base[2 * CH + d];

    if (SHIFT) {
        int ry = sy < 56 ? 0 : (sy < 60 ? 1 : 2);
        int rx = sx < 56 ? 0 : (sx < 60 ? 1 : 2);
        scode[n] = ry * 3 + rx;
    }
    for (int i = n; i < 225; i += 64) sbias[i] = rpb[i * HEADS + head];
    __syncthreads();

    float s[64];
    const int mycode = SHIFT ? scode[n] : 0;
    #pragma unroll
    for (int m = 0; m < 64; m++) {
        float a = 0.f;
        #pragma unroll
        for (int d = 0; d < HD; d++) a += q[d] * Ks[m][d];
        int r2 = m >> 3, c2 = m & 7;
        a += sbias[(r - r2 + 7) * 15 + (c - c2 + 7)];
        if (SHIFT) { if (mycode != scode[m]) a -= 100.0f; }
        s[m] = a;
    }
    float mx = -1e30f;
    #pragma unroll
    for (int m = 0; m < 64; m++) mx = fmaxf(mx, s[m]);
    float sum = 0.f;
    #pragma unroll
    for (int m = 0; m < 64; m++) { s[m] = expf(s[m] - mx); sum += s[m]; }
    const float inv = 1.0f / sum;
    float acc[HD] = {};
    #pragma unroll
    for (int m = 0; m < 64; m++) {
        float p = s[m] * inv;
        #pragma unroll
        for (int d = 0; d < HD; d++) acc[d] += p * Vs[m][d];
    }
    size_t ob = (size_t)t * CH + head * HD;
    #pragma unroll
    for (int d = 0; d < HD; d++) {
        __nv_bfloat16 h, l;
        split_bf16(acc[d], h, l);
        outh[ob + d] = h;
        outl[ob + d] = l;
    }
}

// ======================= host orchestration =================================
struct Bufs {
    float *qkv, *xb, *yb;
    __nv_bfloat16 *lnh, *lnl, *ath, *atl, *mph, *mpl, *wth, *wtl;
};

static inline void launch_gemm(int epi, const __nv_bfloat16* Ah, const __nv_bfloat16* Al,
                               const __nv_bfloat16* Bh, const __nv_bfloat16* Bl,
                               const float* bias, const float* res, float* out,
                               __nv_bfloat16* oh, __nv_bfloat16* ol, int N, int K) {
    dim3 grid(N / 128, TOK / 128);
    if (epi == 0)      tc_gemm<0><<<grid, 256, SM_DYN>>>(Ah, Al, Bh, Bl, bias, res, out, oh, ol, TOK, N, K);
    else if (epi == 1) tc_gemm<1><<<grid, 256, SM_DYN>>>(Ah, Al, Bh, Bl, bias, res, out, oh, ol, TOK, N, K);
    else               tc_gemm<2><<<grid, 256, SM_DYN>>>(Ah, Al, Bh, Bl, bias, res, out, oh, ol, TOK, N, K);
}

extern "C" void kernel_launch(void* const* d_in, const int* in_sizes, int n_in,
                              void* d_out, int out_size) {
    const float* x = (const float*)d_in[0];
    const float* p0[13];
    const float* p1[13];
    for (int i = 0; i < 13; i++) p0[i] = (const float*)d_in[1 + i];
    for (int i = 0; i < 13; i++) p1[i] = (const float*)d_in[14 + i];

    Bufs b;
    cudaGetSymbolAddress((void**)&b.qkv, g_qkv);
    cudaGetSymbolAddress((void**)&b.xb,  g_x);
    cudaGetSymbolAddress((void**)&b.yb,  g_y);
    cudaGetSymbolAddress((void**)&b.lnh, g_lnh);
    cudaGetSymbolAddress((void**)&b.lnl, g_lnl);
    cudaGetSymbolAddress((void**)&b.ath, g_ath);
    cudaGetSymbolAddress((void**)&b.atl, g_atl);
    cudaGetSymbolAddress((void**)&b.mph, g_mph);
    cudaGetSymbolAddress((void**)&b.mpl, g_mpl);
    cudaGetSymbolAddress((void**)&b.wth, g_wth);
    cudaGetSymbolAddress((void**)&b.wtl, g_wtl);

    cudaFuncSetAttribute(tc_gemm<0>, cudaFuncAttributeMaxDynamicSharedMemorySize, SM_DYN);
    cudaFuncSetAttribute(tc_gemm<1>, cudaFuncAttributeMaxDynamicSharedMemorySize, SM_DYN);
    cudaFuncSetAttribute(tc_gemm<2>, cudaFuncAttributeMaxDynamicSharedMemorySize, SM_DYN);

    // ---- weight prep: transpose + hi/lo split ----
    const float* srcs[2][4] = {{p0[2], p0[5], p0[9], p0[11]}, {p1[2], p1[5], p1[9], p1[11]}};
    const int KK[4]  = {256, 256, 256, 1024};
    const int NN[4]  = {768, 256, 1024, 256};
    const int OFF[4] = {0, 196608, 262144, 524288};
    for (int blk = 0; blk < 2; blk++)
        for (int w = 0; w < 4; w++)
            transpose_split<<<dim3(NN[w] / 32, KK[w] / 32), dim3(32, 8)>>>(
                srcs[blk][w], b.wth + blk * WT_BLK + OFF[w], b.wtl + blk * WT_BLK + OFF[w],
                KK[w], NN[w]);

    for (int blk = 0; blk < 2; blk++) {
        const float* const* p = blk ? p1 : p0;
        const float* xin = blk ? b.xb : x;
        float* xout = blk ? b.yb : b.xb;
        __nv_bfloat16* wh = b.wth + blk * WT_BLK;
        __nv_bfloat16* wl = b.wtl + blk * WT_BLK;
        float* fin = blk ? (float*)d_out : b.xb;

        ln_kernel<<<TOK, 256>>>(xin, p[0], p[1], b.lnh, b.lnl);
        launch_gemm(0, b.lnh, b.lnl, wh + 0, wl + 0, p[3], nullptr, b.qkv, nullptr, nullptr, 768, 256);
        if (blk)
            attn_kernel<4><<<dim3(HEADS, 64, 16), 64>>>(b.qkv, p[4], b.ath, b.atl);
        else
            attn_kernel<0><<<dim3(HEADS, 64, 16), 64>>>(b.qkv, p[4], b.ath, b.atl);
        launch_gemm(2, b.ath, b.atl, wh + 196608, wl + 196608, p[6], xin, xout, nullptr, nullptr, 256, 256);
        ln_kernel<<<TOK, 256>>>(xout, p[7], p[8], b.lnh, b.lnl);
        launch_gemm(1, b.lnh, b.lnl, wh + 262144, wl + 262144, p[10], nullptr, nullptr, b.mph, b.mpl, 1024, 256);
        launch_gemm(2, b.mph, b.mpl, wh + 524288, wl + 524288, p[12], xout, fin, nullptr, nullptr, 256, 1024);
    }
}

// round 8
// speedup vs baseline: 2.5440x; 1.3695x over previous
#include <cuda_runtime.h>
#include <cuda_bf16.h>
#include <math.h>
#include <stdint.h>

#define TOK   65536
#define CH    256
#define HEADS 8
#define HD    32
#define WS    8
#define MLPH  1024

// ---------------- scratch (static device globals; no allocation) -----------
__device__ float          g_qkv [TOK * 3 * CH];
__device__ float          g_x   [TOK * CH];
__device__ float          g_y   [TOK * CH];
__device__ __nv_bfloat16  g_lnh [TOK * CH];
__device__ __nv_bfloat16  g_lnl [TOK * CH];
__device__ __nv_bfloat16  g_ath [TOK * CH];
__device__ __nv_bfloat16  g_atl [TOK * CH];
__device__ __nv_bfloat16  g_mph [TOK * MLPH];
__device__ __nv_bfloat16  g_mpl [TOK * MLPH];
#define WT_BLK 786432
__device__ __nv_bfloat16  g_wth [2 * WT_BLK];
__device__ __nv_bfloat16  g_wtl [2 * WT_BLK];

// ======================= small PTX helpers =================================
__device__ __forceinline__ uint32_t smem_u32(const void* p) {
    uint32_t a;
    asm("{ .reg .u64 t; cvta.to.shared.u64 t, %1; cvt.u32.u64 %0, t; }" : "=r"(a) : "l"(p));
    return a;
}
__device__ __forceinline__ void cp16(uint32_t s, const void* g) {
    asm volatile("cp.async.ca.shared.global [%0], [%1], 16;" :: "r"(s), "l"(g));
}
#define CP_COMMIT() asm volatile("cp.async.commit_group;" ::: "memory")
#define CP_WAIT(n)  asm volatile("cp.async.wait_group %0;" :: "n"(n) : "memory")

__device__ __forceinline__ void ld_x4(uint32_t* r, uint32_t addr) {
    asm volatile("ldmatrix.sync.aligned.m8n8.x4.shared.b16 {%0,%1,%2,%3}, [%4];"
                 : "=r"(r[0]), "=r"(r[1]), "=r"(r[2]), "=r"(r[3]) : "r"(addr));
}
__device__ __forceinline__ void mma16816(float* c, const uint32_t* a, const uint32_t* b) {
    asm volatile("mma.sync.aligned.m16n8k16.row.col.f32.bf16.bf16.f32 "
                 "{%0,%1,%2,%3}, {%4,%5,%6,%7}, {%8,%9}, {%0,%1,%2,%3};"
                 : "+f"(c[0]), "+f"(c[1]), "+f"(c[2]), "+f"(c[3])
                 : "r"(a[0]), "r"(a[1]), "r"(a[2]), "r"(a[3]), "r"(b[0]), "r"(b[1]));
}
__device__ __forceinline__ void split_bf16(float v, __nv_bfloat16& h, __nv_bfloat16& l) {
    h = __float2bfloat16(v);
    l = __float2bfloat16(v - __bfloat162float(h));
}
__device__ __forceinline__ float gelu_exact(float x) {
    return 0.5f * x * (1.0f + erff(x * 0.7071067811865476f));
}

// ============ LayerNorm: 4 tokens/block, 64 threads/token, float4 ==========
__global__ __launch_bounds__(256)
void ln_kernel(const float* __restrict__ in, const float* __restrict__ gam,
               const float* __restrict__ bet,
               __nv_bfloat16* __restrict__ oh, __nv_bfloat16* __restrict__ ol) {
    const int tid = threadIdx.x;
    const int g = tid >> 6;                  // token slot 0..3
    const int l64 = tid & 63;                // thread within token
    const int w = (tid >> 5) & 1;            // warp half within token group
    const int tok = blockIdx.x * 4 + g;

    __shared__ float redm[4][2];
    __shared__ float redv[4][2];

    const size_t base = (size_t)tok * CH + l64 * 4;
    float4 v = *(const float4*)(in + base);

    float s = v.x + v.y + v.z + v.w;
    #pragma unroll
    for (int o = 16; o; o >>= 1) s += __shfl_xor_sync(0xffffffffu, s, o);
    if ((tid & 31) == 0) redm[g][w] = s;
    __syncthreads();
    const float mu = (redm[g][0] + redm[g][1]) * (1.0f / CH);

    float dx = v.x - mu, dy = v.y - mu, dz = v.z - mu, dw = v.w - mu;
    s = dx * dx + dy * dy + dz * dz + dw * dw;
    #pragma unroll
    for (int o = 16; o; o >>= 1) s += __shfl_xor_sync(0xffffffffu, s, o);
    if ((tid & 31) == 0) redv[g][w] = s;
    __syncthreads();
    const float inv = rsqrtf((redv[g][0] + redv[g][1]) * (1.0f / CH) + 1e-5f);

    const float4 gm = *(const float4*)(gam + l64 * 4);
    const float4 bt = *(const float4*)(bet + l64 * 4);
    float o0 = dx * inv * gm.x + bt.x;
    float o1 = dy * inv * gm.y + bt.y;
    float o2 = dz * inv * gm.z + bt.z;
    float o3 = dw * inv * gm.w + bt.w;

    __nv_bfloat16 h[4], lo[4];
    split_bf16(o0, h[0], lo[0]); split_bf16(o1, h[1], lo[1]);
    split_bf16(o2, h[2], lo[2]); split_bf16(o3, h[3], lo[3]);
    *(uint2*)(oh + base) = *(uint2*)h;
    *(uint2*)(ol + base) = *(uint2*)lo;
}

// ========== weight prep: W[K,N] -> Wt_hi[N,K], Wt_lo[N,K] (bf16) ===========
__global__ void transpose_split(const float* __restrict__ W, __nv_bfloat16* __restrict__ th,
                                __nv_bfloat16* __restrict__ tl, int K, int N) {
    __shared__ float t[32][33];
    int nb = blockIdx.x << 5, kb = blockIdx.y << 5;
    #pragma unroll
    for (int i = 0; i < 32; i += 8)
        t[threadIdx.y + i][threadIdx.x] = W[(size_t)(kb + threadIdx.y + i) * N + nb + threadIdx.x];
    __syncthreads();
    #pragma unroll
    for (int i = 0; i < 32; i += 8) {
        float v = t[threadIdx.x][threadIdx.y + i];
        __nv_bfloat16 h, l;
        split_bf16(v, h, l);
        size_t off = (size_t)(nb + threadIdx.y + i) * K + kb + threadIdx.x;
        th[off] = h; tl[off] = l;
    }
}

// ======================= split-bf16 HMMA GEMM ==============================
// C[M,N] = A @ Wt^T (3-pass: Ah*Bh + Ah*Bl + Al*Bh), bias + epilogue.
// EPI: 0 = fp32 out;  1 = GELU -> (hi,lo) bf16 out;  2 = +res -> fp32 out.
#define TS 40                         // smem row stride in halves (80 B)
#define TILE_B (128 * TS * 2)         // 10240 B per tile
#define STAGE_B (4 * TILE_B)          // Ah, Al, Bh, Bl
#define NSTAGE 3
#define SM_BIAS (NSTAGE * STAGE_B)
#define SM_DYN  (SM_BIAS + 512)

template <int EPI>
__global__ __launch_bounds__(256, 1)
void tc_gemm(const __nv_bfloat16* __restrict__ Ah, const __nv_bfloat16* __restrict__ Al,
             const __nv_bfloat16* __restrict__ Bh, const __nv_bfloat16* __restrict__ Bl,
             const float* __restrict__ bias, const float* __restrict__ res,
             float* __restrict__ out, __nv_bfloat16* __restrict__ outh,
             __nv_bfloat16* __restrict__ outl, int M, int N, int K) {
    extern __shared__ char sm[];
    const uint32_t sb = smem_u32(sm);
    const int tid = threadIdx.x, wid = tid >> 5, lane = tid & 31;
    const int n0 = blockIdx.x << 7, m0 = blockIdx.y << 7;
    const int mw = wid >> 2, nw = wid & 3;          // warp grid 2x4 -> 64x32 tiles

    float* sbias = (float*)(sm + SM_BIAS);
    if (tid < 128) sbias[tid] = bias[n0 + tid];

    // ---- async load of one pipeline stage ----
    const int lrow = tid >> 2, lc = tid & 3;
    auto load_stage = [&](int s, int kc) {
        const int k0 = kc << 5;
        uint32_t base = sb + s * STAGE_B;
        #pragma unroll
        for (int i = 0; i < 2; i++) {
            int row = lrow + i * 64;
            uint32_t so = row * (TS * 2) + lc * 16;
            size_t ga = (size_t)(m0 + row) * K + k0 + lc * 8;
            size_t gb = (size_t)(n0 + row) * K + k0 + lc * 8;
            cp16(base + 0 * TILE_B + so, Ah + ga);
            cp16(base + 1 * TILE_B + so, Al + ga);
            cp16(base + 2 * TILE_B + so, Bh + gb);
            cp16(base + 3 * TILE_B + so, Bl + gb);
        }
    };

    float acc[4][4][4] = {};

    const int li = lane & 7, lm = lane >> 3;
    const uint32_t aRB = (mw * 64 + (lm & 1) * 8 + li) * (TS * 2) + ((lm >> 1) * 8) * 2;
    const uint32_t bRB = (nw * 32 + (lm >> 1) * 8 + li) * (TS * 2) + ((lm & 1) * 8) * 2;

    const int nch = K >> 5;
    load_stage(0, 0); CP_COMMIT();
    load_stage(1, 1); CP_COMMIT();

    int s = 0;
    for (int kc = 0; kc < nch; kc++) {
        if (kc + 1 < nch) CP_WAIT(1); else CP_WAIT(0);
        __syncthreads();

        const uint32_t sA  = sb + s * STAGE_B;
        const uint32_t sAl = sA + TILE_B;
        const uint32_t sB  = sA + 2 * TILE_B;
        const uint32_t sBl = sA + 3 * TILE_B;

        #pragma unroll
        for (int kk = 0; kk < 2; kk++) {
            const uint32_t ko = kk * 32;
            uint32_t ah[16], al[16], bh[8], bl[8];
            #pragma unroll
            for (int mg = 0; mg < 4; mg++) ld_x4(ah + mg * 4, sA + aRB + mg * 16 * (TS * 2) + ko);
            #pragma unroll
            for (int ng = 0; ng < 2; ng++) ld_x4(bh + ng * 4, sB + bRB + ng * 16 * (TS * 2) + ko);
            #pragma unroll
            for (int mg = 0; mg < 4; mg++)
                #pragma unroll
                for (int j = 0; j < 4; j++)
                    mma16816(acc[mg][j], ah + mg * 4, bh + (j >> 1) * 4 + (j & 1) * 2);
            #pragma unroll
            for (int ng = 0; ng < 2; ng++) ld_x4(bl + ng * 4, sBl + bRB + ng * 16 * (TS * 2) + ko);
            #pragma unroll
            for (int mg = 0; mg < 4; mg++)
                #pragma unroll
                for (int j = 0; j < 4; j++)
                    mma16816(acc[mg][j], ah + mg * 4, bl + (j >> 1) * 4 + (j & 1) * 2);
            #pragma unroll
            for (int mg = 0; mg < 4; mg++) ld_x4(al + mg * 4, sAl + aRB + mg * 16 * (TS * 2) + ko);
            #pragma unroll
            for (int mg = 0; mg < 4; mg++)
                #pragma unroll
                for (int j = 0; j < 4; j++)
                    mma16816(acc[mg][j], al + mg * 4, bh + (j >> 1) * 4 + (j & 1) * 2);
        }

        if (kc + 2 < nch) { load_stage((kc + 2) % NSTAGE, kc + 2); CP_COMMIT(); }
        s = (s + 1 == NSTAGE) ? 0 : s + 1;
    }
    __syncthreads();                            // all warps done with stages

    // ---- epilogue: regs -> smem (fp32) -> coalesced gmem ----
    float* sacc = (float*)sm;                   // 128 x 132 floats (overlaps stages)
    const int fr = lane >> 2, fc = (lane & 3) * 2;
    #pragma unroll
    for (int mg = 0; mg < 4; mg++)
        #pragma unroll
        for (int j = 0; j < 4; j++) {
            int row = mw * 64 + mg * 16 + fr;
            int col = nw * 32 + j * 8 + fc;
            sacc[row * 132 + col]           = acc[mg][j][0];
            sacc[row * 132 + col + 1]       = acc[mg][j][1];
            sacc[(row + 8) * 132 + col]     = acc[mg][j][2];
            sacc[(row + 8) * 132 + col + 1] = acc[mg][j][3];
        }
    __syncthreads();

    const float4 b4 = *(const float4*)&sbias[lane * 4];
    #pragma unroll 4
    for (int it = 0; it < 16; it++) {
        int r = it * 8 + wid;
        float4 v = *(const float4*)&sacc[r * 132 + lane * 4];
        v.x += b4.x; v.y += b4.y; v.z += b4.z; v.w += b4.w;
        size_t off = (size_t)(m0 + r) * N + n0 + lane * 4;
        if (EPI == 0) {
            *(float4*)&out[off] = v;
        } else if (EPI == 1) {
            v.x = gelu_exact(v.x); v.y = gelu_exact(v.y);
            v.z = gelu_exact(v.z); v.w = gelu_exact(v.w);
            __nv_bfloat16 h[4], l[4];
            split_bf16(v.x, h[0], l[0]); split_bf16(v.y, h[1], l[1]);
            split_bf16(v.z, h[2], l[2]); split_bf16(v.w, h[3], l[3]);
            *(uint2*)&outh[off] = *(uint2*)h;
            *(uint2*)&outl[off] = *(uint2*)l;
        } else {
            float4 rv = *(const float4*)&res[off];
            v.x += rv.x; v.y += rv.y; v.z += rv.z; v.w += rv.w;
            *(float4*)&out[off] = v;
        }
    }
}

// ======================= windowed attention (fp32, emits hi/lo) ============
template <int SHIFT>
__global__ __launch_bounds__(64)
void attn_kernel(const float* __restrict__ qkv, const float* __restrict__ rpb,
                 __nv_bfloat16* __restrict__ outh, __nv_bfloat16* __restrict__ outl) {
    const int head = blockIdx.x, win = blockIdx.y, b = blockIdx.z;
    const int wy = win >> 3, wx = win & 7;
    const int n = threadIdx.x;
    const int r = n >> 3, c = n & 7;

    __shared__ float Ks[64][HD];
    __shared__ float Vs[64][HD];
    __shared__ float sbias[225];
    __shared__ int   scode[64];

    const int sy = wy * WS + r, sx = wx * WS + c;
    const int y = (sy + SHIFT) & 63;
    const int x = (sx + SHIFT) & 63;
    const int t = b * 4096 + y * 64 + x;

    const float4* base = (const float4*)(qkv + (size_t)t * (3 * CH) + head * HD);
    float q[HD];
    #pragma unroll
    for (int i = 0; i < 8; i++) {
        float4 u = base[i];
        q[i * 4 + 0] = u.x * 0.17677669529663687f;
        q[i * 4 + 1] = u.y * 0.17677669529663687f;
        q[i * 4 + 2] = u.z * 0.17677669529663687f;
        q[i * 4 + 3] = u.w * 0.17677669529663687f;
    }
    #pragma unroll
    for (int i = 0; i < 8; i++) *(float4*)&Ks[n][i * 4] = base[64 + i];
    #pragma unroll
    for (int i = 0; i < 8; i++) *(float4*)&Vs[n][i * 4] = base[128 + i];

    if (SHIFT) {
        int ry = sy < 56 ? 0 : (sy < 60 ? 1 : 2);
        int rx = sx < 56 ? 0 : (sx < 60 ? 1 : 2);
        scode[n] = ry * 3 + rx;
    }
    for (int i = n; i < 225; i += 64) sbias[i] = rpb[i * HEADS + head];
    __syncthreads();

    float s[64];
    const int mycode = SHIFT ? scode[n] : 0;
    #pragma unroll
    for (int m = 0; m < 64; m++) {
        float a = 0.f;
        #pragma unroll
        for (int d = 0; d < HD; d++) a += q[d] * Ks[m][d];
        int r2 = m >> 3, c2 = m & 7;
        a += sbias[(r - r2 + 7) * 15 + (c - c2 + 7)];
        if (SHIFT) { if (mycode != scode[m]) a -= 100.0f; }
        s[m] = a;
    }
    float mx = -1e30f;
    #pragma unroll
    for (int m = 0; m < 64; m++) mx = fmaxf(mx, s[m]);
    float sum = 0.f;
    #pragma unroll
    for (int m = 0; m < 64; m++) { s[m] = expf(s[m] - mx); sum += s[m]; }
    const float inv = 1.0f / sum;
    float acc[HD] = {};
    #pragma unroll
    for (int m = 0; m < 64; m++) {
        float p = s[m] * inv;
        #pragma unroll
        for (int d = 0; d < HD; d++) acc[d] += p * Vs[m][d];
    }
    size_t ob = (size_t)t * CH + head * HD;
    #pragma unroll
    for (int i = 0; i < 8; i++) {
        __nv_bfloat16 h[4], l[4];
        split_bf16(acc[i * 4 + 0], h[0], l[0]);
        split_bf16(acc[i * 4 + 1], h[1], l[1]);
        split_bf16(acc[i * 4 + 2], h[2], l[2]);
        split_bf16(acc[i * 4 + 3], h[3], l[3]);
        *(uint2*)(outh + ob + i * 4) = *(uint2*)h;
        *(uint2*)(outl + ob + i * 4) = *(uint2*)l;
    }
}

// ======================= host orchestration =================================
struct Bufs {
    float *qkv, *xb, *yb;
    __nv_bfloat16 *lnh, *lnl, *ath, *atl, *mph, *mpl, *wth, *wtl;
};

static inline void launch_gemm(int epi, const __nv_bfloat16* Ah, const __nv_bfloat16* Al,
                               const __nv_bfloat16* Bh, const __nv_bfloat16* Bl,
                               const float* bias, const float* res, float* out,
                               __nv_bfloat16* oh, __nv_bfloat16* ol, int N, int K) {
    dim3 grid(N / 128, TOK / 128);
    if (epi == 0)      tc_gemm<0><<<grid, 256, SM_DYN>>>(Ah, Al, Bh, Bl, bias, res, out, oh, ol, TOK, N, K);
    else if (epi == 1) tc_gemm<1><<<grid, 256, SM_DYN>>>(Ah, Al, Bh, Bl, bias, res, out, oh, ol, TOK, N, K);
    else               tc_gemm<2><<<grid, 256, SM_DYN>>>(Ah, Al, Bh, Bl, bias, res, out, oh, ol, TOK, N, K);
}

extern "C" void kernel_launch(void* const* d_in, const int* in_sizes, int n_in,
                              void* d_out, int out_size) {
    const float* x = (const float*)d_in[0];
    const float* p0[13];
    const float* p1[13];
    for (int i = 0; i < 13; i++) p0[i] = (const float*)d_in[1 + i];
    for (int i = 0; i < 13; i++) p1[i] = (const float*)d_in[14 + i];

    Bufs b;
    cudaGetSymbolAddress((void**)&b.qkv, g_qkv);
    cudaGetSymbolAddress((void**)&b.xb,  g_x);
    cudaGetSymbolAddress((void**)&b.yb,  g_y);
    cudaGetSymbolAddress((void**)&b.lnh, g_lnh);
    cudaGetSymbolAddress((void**)&b.lnl, g_lnl);
    cudaGetSymbolAddress((void**)&b.ath, g_ath);
    cudaGetSymbolAddress((void**)&b.atl, g_atl);
    cudaGetSymbolAddress((void**)&b.mph, g_mph);
    cudaGetSymbolAddress((void**)&b.mpl, g_mpl);
    cudaGetSymbolAddress((void**)&b.wth, g_wth);
    cudaGetSymbolAddress((void**)&b.wtl, g_wtl);

    cudaFuncSetAttribute(tc_gemm<0>, cudaFuncAttributeMaxDynamicSharedMemorySize, SM_DYN);
    cudaFuncSetAttribute(tc_gemm<1>, cudaFuncAttributeMaxDynamicSharedMemorySize, SM_DYN);
    cudaFuncSetAttribute(tc_gemm<2>, cudaFuncAttributeMaxDynamicSharedMemorySize, SM_DYN);

    // ---- weight prep: transpose + hi/lo split ----
    const float* srcs[2][4] = {{p0[2], p0[5], p0[9], p0[11]}, {p1[2], p1[5], p1[9], p1[11]}};
    const int KK[4]  = {256, 256, 256, 1024};
    const int NN[4]  = {768, 256, 1024, 256};
    const int OFF[4] = {0, 196608, 262144, 524288};
    for (int blk = 0; blk < 2; blk++)
        for (int w = 0; w < 4; w++)
            transpose_split<<<dim3(NN[w] / 32, KK[w] / 32), dim3(32, 8)>>>(
                srcs[blk][w], b.wth + blk * WT_BLK + OFF[w], b.wtl + blk * WT_BLK + OFF[w],
                KK[w], NN[w]);

    for (int blk = 0; blk < 2; blk++) {
        const float* const* p = blk ? p1 : p0;
        const float* xin = blk ? b.xb : x;
        float* xout = blk ? b.yb : b.xb;
        __nv_bfloat16* wh = b.wth + blk * WT_BLK;
        __nv_bfloat16* wl = b.wtl + blk * WT_BLK;
        float* fin = blk ? (float*)d_out : b.xb;

        ln_kernel<<<TOK / 4, 256>>>(xin, p[0], p[1], b.lnh, b.lnl);
        launch_gemm(0, b.lnh, b.lnl, wh + 0, wl + 0, p[3], nullptr, b.qkv, nullptr, nullptr, 768, 256);
        if (blk)
            attn_kernel<4><<<dim3(HEADS, 64, 16), 64>>>(b.qkv, p[4], b.ath, b.atl);
        else
            attn_kernel<0><<<dim3(HEADS, 64, 16), 64>>>(b.qkv, p[4], b.ath, b.atl);
        launch_gemm(2, b.ath, b.atl, wh + 196608, wl + 196608, p[6], xin, xout, nullptr, nullptr, 256, 256);
        ln_kernel<<<TOK / 4, 256>>>(xout, p[7], p[8], b.lnh, b.lnl);
        launch_gemm(1, b.lnh, b.lnl, wh + 262144, wl + 262144, p[10], nullptr, nullptr, b.mph, b.mpl, 1024, 256);
        launch_gemm(2, b.mph, b.mpl, wh + 524288, wl + 524288, p[12], xout, fin, nullptr, nullptr, 256, 1024);
    }
}